// round 1
// baseline (speedup 1.0000x reference)
#include <cuda_runtime.h>
#include <math.h>

#define N_G   1024
#define KW    5
#define NS    (N_G * KW * KW)      // 25600 samples
#define SCALE 1.0f
#define DXC   (2.0f / 31.0f)
#define QCUT  60.0f                // exp(-30) ~ 1e-13: dropped terms are negligible
#define GPB   16                   // gaussians per block in the net kernel

// Scratch (device globals -- no allocation allowed)
__device__ float4 d_gA[N_G];          // mx, my, r2max, u
__device__ float4 d_gB[N_G];          // a, b, c, trace(conic)
__device__ float  d_img[N_G * 75];    // (N, 3, 5, 5) flattened: c*25 + kx*5 + ky

// ---------------------------------------------------------------------------
// Kernel 1: per-Gaussian conic + prune radius
// cov = L L^T, L = [[s0,0],[t,s1]] -> cov = [[s0^2, s0 t],[s0 t, t^2+s1^2]]
// conic = cov^{-1}; q >= d^2 / lambda_max(cov), so skip when d^2 > QCUT*lmax.
// ---------------------------------------------------------------------------
__global__ void k_prep(const float* __restrict__ means,
                       const float* __restrict__ u,
                       const float* __restrict__ scaling,
                       const float* __restrict__ transform)
{
    int i = blockIdx.x * blockDim.x + threadIdx.x;
    if (i >= N_G) return;
    float s0 = scaling[i * 2 + 0];
    float s1 = scaling[i * 2 + 1];
    float t  = transform[i];
    float A = s0 * s0;
    float B = s0 * t;
    float C = t * t + s1 * s1;
    float inv = 1.0f / (A * C - B * B);
    float a =  C * inv;
    float b = -B * inv;
    float c =  A * inv;
    float h = 0.5f * (A + C);
    float r = sqrtf(0.25f * (A - C) * (A - C) + B * B);
    float lmax = h + r;
    d_gA[i] = make_float4(means[i * 2 + 0], means[i * 2 + 1], QCUT * lmax, u[i]);
    d_gB[i] = make_float4(a, b, c, a + c);
}

// ---------------------------------------------------------------------------
// Kernel 2: mixture evaluation at all 25600 sample points.
// Per sample: u_s = sum_j w_j,  pde = sum_j w_j*(Cd0^2+Cd1^2 - tr(C_j)),
// with w_j = exp(-q/2)*u_j. Fast path: 1 LDS.128 + distance test.
// ---------------------------------------------------------------------------
__global__ void __launch_bounds__(256) k_samples()
{
    __shared__ float4 sA[N_G];
    __shared__ float4 sB[N_G];
    for (int j = threadIdx.x; j < N_G; j += blockDim.x) {
        sA[j] = d_gA[j];
        sB[j] = d_gB[j];
    }
    __syncthreads();

    int s = blockIdx.x * blockDim.x + threadIdx.x;
    if (s >= NS) return;
    int i  = s / 25;
    int k  = s % 25;
    int kx = k / 5;
    int ky = k % 5;

    float4 gi = sA[i];
    float sx = gi.x + (float)(kx - 2) * DXC;
    float sy = gi.y + (float)(ky - 2) * DXC;

    float us = 0.0f, pd = 0.0f;
    #pragma unroll 4
    for (int j = 0; j < N_G; ++j) {
        float4 A = sA[j];
        float dx = sx - A.x;
        float dy = sy - A.y;
        float d2 = dx * dx + dy * dy;
        if (d2 <= A.z) {
            float4 Bv = sB[j];
            float Cd0 = Bv.x * dx + Bv.y * dy;
            float Cd1 = Bv.y * dx + Bv.z * dy;
            float q   = dx * Cd0 + dy * Cd1;
            float w   = __expf(-0.5f * q) * A.w;
            us += w;
            pd += w * (Cd0 * Cd0 + Cd1 * Cd1 - Bv.w);
        }
    }
    float mask = (fabsf(sx) < SCALE && fabsf(sy) < SCALE) ? 1.0f : 0.0f;
    d_img[i * 75 +  0 + k] = us;
    d_img[i * 75 + 25 + k] = pd;
    d_img[i * 75 + 50 + k] = mask;
}

// ---------------------------------------------------------------------------
// Kernel 3: the 4 stacked networks. grid = (4 nets, 64 groups of 16 gaussians)
// blockDim = 128. Net weights cached in smem (~44 KB).
// ---------------------------------------------------------------------------
__global__ void __launch_bounds__(128) k_net(
    const float* __restrict__ conv_w, const float* __restrict__ conv_b,
    const float* __restrict__ emb_w,  const float* __restrict__ emb_b,
    const float* __restrict__ lin1_w, const float* __restrict__ lin1_b,
    const float* __restrict__ sol_w,  const float* __restrict__ sol_b,
    const float* __restrict__ tr_w,   const float* __restrict__ tr_b,
    const float* __restrict__ sc_w,   const float* __restrict__ sc_b,
    const float* __restrict__ tf_w,   const float* __restrict__ tf_b,
    const float* __restrict__ means,  const float* __restrict__ u,
    const float* __restrict__ scaling,const float* __restrict__ transform,
    float* __restrict__ out)
{
    __shared__ float swc[50 * 75];
    __shared__ float swe[6 * 30];
    __shared__ float swl[80 * 80];
    __shared__ float sbc[50], sbe[30], sbl[80];
    __shared__ float shw[160];   // head weights (up to 80x2)
    __shared__ float shb[2];
    __shared__ float simg[75], sprm[6], sh[80], sh2[80];

    const int m   = blockIdx.x;   // network index 0..3
    const int tid = threadIdx.x;

    for (int idx = tid; idx < 50 * 75; idx += blockDim.x) swc[idx] = conv_w[m * 3750 + idx];
    for (int idx = tid; idx < 180;     idx += blockDim.x) swe[idx] = emb_w[m * 180 + idx];
    for (int idx = tid; idx < 6400;    idx += blockDim.x) swl[idx] = lin1_w[m * 6400 + idx];
    if (tid < 50) sbc[tid] = conv_b[m * 50 + tid];
    if (tid < 30) sbe[tid] = emb_b[m * 30 + tid];
    if (tid < 80) sbl[tid] = lin1_b[m * 80 + tid];

    const float* hw; const float* hb; int od;
    if      (m == 0) { hw = sol_w; hb = sol_b; od = 1; }
    else if (m == 1) { hw = tr_w;  hb = tr_b;  od = 2; }
    else if (m == 2) { hw = sc_w;  hb = sc_b;  od = 2; }
    else             { hw = tf_w;  hb = tf_b;  od = 1; }
    for (int idx = tid; idx < 80 * od; idx += blockDim.x) shw[idx] = hw[idx];
    if (tid < od) shb[tid] = hb[tid];
    __syncthreads();

    const int g0 = blockIdx.y * GPB;
    for (int gi = 0; gi < GPB; ++gi) {
        const int i = g0 + gi;
        if (tid < 75) simg[tid] = d_img[i * 75 + tid];
        if (tid >= 96 && tid < 102) {
            int p = tid - 96;
            float v;
            if      (p < 2)  v = means[i * 2 + p];
            else if (p == 2) v = u[i];
            else if (p < 5)  v = scaling[i * 2 + (p - 3)];
            else             v = transform[i];
            sprm[p] = v;
        }
        __syncthreads();

        // stage 1: conv (tid<50) + embedding (50<=tid<80)
        if (tid < 50) {
            float acc = sbc[tid];
            const float* wrow = &swc[tid * 75];
            #pragma unroll 5
            for (int k2 = 0; k2 < 75; ++k2) acc = fmaf(simg[k2], wrow[k2], acc);
            sh[tid] = tanhf(acc);
        } else if (tid < 80) {
            int q = tid - 50;
            float acc = sbe[q];
            #pragma unroll
            for (int p = 0; p < 6; ++p) acc = fmaf(sprm[p], swe[p * 30 + q], acc);
            sh[tid] = tanhf(acc);
        }
        __syncthreads();

        // stage 2: 80x80
        if (tid < 80) {
            float acc = sbl[tid];
            #pragma unroll 8
            for (int p = 0; p < 80; ++p) acc = fmaf(sh[p], swl[p * 80 + tid], acc);
            sh2[tid] = tanhf(acc);
        }
        __syncthreads();

        // stage 3: head + residual update
        if (tid < od) {
            float acc = shb[tid];
            #pragma unroll 8
            for (int p = 0; p < 80; ++p) acc = fmaf(sh2[p], shw[p * od + tid], acc);
            if      (m == 0) out[i * 6 + 0]       = sprm[2] + acc;
            else if (m == 1) out[i * 6 + 1 + tid] = sprm[tid] + acc;
            else if (m == 2) out[i * 6 + 3 + tid] = sprm[3 + tid] * expf(acc);
            else             out[i * 6 + 5]       = sprm[5] + acc;
        }
        __syncthreads();
    }
}

// ---------------------------------------------------------------------------
extern "C" void kernel_launch(void* const* d_in, const int* in_sizes, int n_in,
                              void* d_out, int out_size)
{
    const float* means     = (const float*)d_in[0];
    const float* u         = (const float*)d_in[1];
    const float* scaling   = (const float*)d_in[2];
    const float* transform = (const float*)d_in[3];
    const float* conv_w    = (const float*)d_in[4];
    const float* conv_b    = (const float*)d_in[5];
    const float* emb_w     = (const float*)d_in[6];
    const float* emb_b     = (const float*)d_in[7];
    const float* lin1_w    = (const float*)d_in[8];
    const float* lin1_b    = (const float*)d_in[9];
    const float* sol_w     = (const float*)d_in[10];
    const float* sol_b     = (const float*)d_in[11];
    const float* tr_w      = (const float*)d_in[12];
    const float* tr_b      = (const float*)d_in[13];
    const float* sc_w      = (const float*)d_in[14];
    const float* sc_b      = (const float*)d_in[15];
    const float* tf_w      = (const float*)d_in[16];
    const float* tf_b      = (const float*)d_in[17];
    float* out             = (float*)d_out;

    k_prep<<<(N_G + 255) / 256, 256>>>(means, u, scaling, transform);
    k_samples<<<NS / 256, 256>>>();
    dim3 grid3(4, N_G / GPB, 1);
    k_net<<<grid3, 128>>>(conv_w, conv_b, emb_w, emb_b, lin1_w, lin1_b,
                          sol_w, sol_b, tr_w, tr_b, sc_w, sc_b, tf_w, tf_b,
                          means, u, scaling, transform, out);
}

// round 2
// speedup vs baseline: 2.7182x; 2.7182x over previous
#include <cuda_runtime.h>
#include <math.h>

#define N_G   1024
#define KW    5
#define NS    (N_G * KW * KW)      // 25600 samples
#define SCALE 1.0f
#define DXC   (2.0f / 31.0f)
#define QCUT  60.0f                // dropped terms < e^-30 * dominant: negligible
#define GPB2  32                   // gaussians per block in net kernel

// Scratch (device globals -- no allocation allowed)
__device__ float d_img[N_G * 75];  // (N, 3, 5, 5): c*25 + kx*5 + ky

__device__ __forceinline__ float tanha(float x) {
    float y;
    asm("tanh.approx.f32 %0, %1;" : "=f"(y) : "f"(x));
    return y;
}

// ---------------------------------------------------------------------------
// Kernel A: fused conic prep + candidate build + mixture evaluation.
// 100 blocks x 256 threads; block = 256 consecutive samples (~10 gaussians).
// ---------------------------------------------------------------------------
__global__ void __launch_bounds__(256) k_samples(
    const float* __restrict__ means, const float* __restrict__ u,
    const float* __restrict__ scaling, const float* __restrict__ transform)
{
    __shared__ float4 sA[N_G];     // mx, my, r2max, u
    __shared__ float4 sB[N_G];     // a, b, c, trace(conic)
    __shared__ int    s_cand[N_G];
    __shared__ int    s_wcnt[8];
    __shared__ int    s_wbase[8];
    __shared__ int    s_total;
    __shared__ float  s_bb[4];     // minx, maxx, miny, maxy
    __shared__ float  s_red[8][4];

    const int tid = threadIdx.x;

    // build gaussian table cooperatively (replaces k_prep)
    for (int i = tid; i < N_G; i += 256) {
        float s0 = scaling[2 * i], s1 = scaling[2 * i + 1], t = transform[i];
        float A = s0 * s0, B = s0 * t, C = t * t + s1 * s1;
        float inv = 1.0f / (A * C - B * B);
        float a =  C * inv;
        float b = -B * inv;
        float c =  A * inv;
        float h = 0.5f * (A + C);
        float r = sqrtf(0.25f * (A - C) * (A - C) + B * B);
        sA[i] = make_float4(means[2 * i], means[2 * i + 1], QCUT * (h + r), u[i]);
        sB[i] = make_float4(a, b, c, a + c);
    }
    if (tid == 0) s_total = 0;
    __syncthreads();

    // this thread's sample position
    const int s  = blockIdx.x * 256 + tid;
    const int i  = s / 25;
    const int k  = s % 25;
    const int kx = k / 5;
    const int ky = k % 5;
    const float4 gi = sA[i];
    const float sx = gi.x + (float)(kx - 2) * DXC;
    const float sy = gi.y + (float)(ky - 2) * DXC;

    // block bbox of sample positions
    float mnx = sx, mxx = sx, mny = sy, mxy = sy;
    #pragma unroll
    for (int o = 16; o > 0; o >>= 1) {
        mnx = fminf(mnx, __shfl_xor_sync(0xffffffffu, mnx, o));
        mxx = fmaxf(mxx, __shfl_xor_sync(0xffffffffu, mxx, o));
        mny = fminf(mny, __shfl_xor_sync(0xffffffffu, mny, o));
        mxy = fmaxf(mxy, __shfl_xor_sync(0xffffffffu, mxy, o));
    }
    if ((tid & 31) == 0) {
        s_red[tid >> 5][0] = mnx; s_red[tid >> 5][1] = mxx;
        s_red[tid >> 5][2] = mny; s_red[tid >> 5][3] = mxy;
    }
    __syncthreads();
    if (tid == 0) {
        float a0 = s_red[0][0], a1 = s_red[0][1], a2 = s_red[0][2], a3 = s_red[0][3];
        for (int w2 = 1; w2 < 8; ++w2) {
            a0 = fminf(a0, s_red[w2][0]); a1 = fmaxf(a1, s_red[w2][1]);
            a2 = fminf(a2, s_red[w2][2]); a3 = fmaxf(a3, s_red[w2][3]);
        }
        s_bb[0] = a0; s_bb[1] = a1; s_bb[2] = a2; s_bb[3] = a3;
    }
    __syncthreads();
    const float bminx = s_bb[0], bmaxx = s_bb[1], bminy = s_bb[2], bmaxy = s_bb[3];

    // deterministic candidate compaction (j-ordered)
    const int wid = tid >> 5, lane = tid & 31;
    for (int c = 0; c < N_G / 256; ++c) {
        int j = c * 256 + tid;
        float4 A = sA[j];
        float ddx = fmaxf(fmaxf(bminx - A.x, A.x - bmaxx), 0.0f);
        float ddy = fmaxf(fmaxf(bminy - A.y, A.y - bmaxy), 0.0f);
        bool pred = (ddx * ddx + ddy * ddy) <= A.z;
        unsigned mask = __ballot_sync(0xffffffffu, pred);
        if (lane == 0) s_wcnt[wid] = __popc(mask);
        __syncthreads();
        if (tid == 0) {
            int acc = s_total;
            for (int w2 = 0; w2 < 8; ++w2) { s_wbase[w2] = acc; acc += s_wcnt[w2]; }
            s_total = acc;
        }
        __syncthreads();
        if (pred) s_cand[s_wbase[wid] + __popc(mask & ((1u << lane) - 1u))] = j;
        __syncthreads();
    }
    const int cnt = s_total;

    // branchless mixture evaluation over candidates (all-broadcast LDS)
    float us = 0.0f, pd = 0.0f;
    for (int t2 = 0; t2 < cnt; ++t2) {
        int j = s_cand[t2];
        float4 A  = sA[j];
        float4 Bv = sB[j];
        float dx = sx - A.x;
        float dy = sy - A.y;
        float Cd0 = Bv.x * dx + Bv.y * dy;
        float Cd1 = Bv.y * dx + Bv.z * dy;
        float q   = dx * Cd0 + dy * Cd1;
        float w   = __expf(-0.5f * q) * A.w;
        us += w;
        pd += w * (Cd0 * Cd0 + Cd1 * Cd1 - Bv.w);
    }
    float maskv = (fabsf(sx) < SCALE && fabsf(sy) < SCALE) ? 1.0f : 0.0f;
    d_img[i * 75 +  0 + k] = us;
    d_img[i * 75 + 25 + k] = pd;
    d_img[i * 75 + 50 + k] = maskv;
}

// ---------------------------------------------------------------------------
// Kernel B: 4 stacked networks, 32 gaussians/block, register-tiled, transposed
// activations [feat][g] (stride 36 -> conflict-free float4 over g).
// grid (4 nets, 32 groups), 256 threads, ~79KB dynamic smem.
// ---------------------------------------------------------------------------
// smem layout (float offsets)
#define OFF_SWC   0        // 50*76   conv w, rows o, k-major (pad 76)
#define OFF_SWE   3800     // 180     emb w [p][q]
#define OFF_SWL   3980     // 80*84   lin1 w rows p, stride 84, q-major
#define OFF_SBC   10700    // 52
#define OFF_SBE   10752    // 32
#define OFF_SBL   10784    // 80
#define OFF_SHW   10864    // 160
#define OFF_SHB   11024    // 4
#define OFF_IMGT  11028    // 75*36   imgT[k][g]
#define OFF_SPRM  13728    // 32*9
#define OFF_SHT   14016    // 80*36   shT[h][g]
#define OFF_SH2T  16896    // 80*36   sh2T[q][g]
#define SMEM_FLTS 19776

__global__ void __launch_bounds__(256) k_net(
    const float* __restrict__ conv_w, const float* __restrict__ conv_b,
    const float* __restrict__ emb_w,  const float* __restrict__ emb_b,
    const float* __restrict__ lin1_w, const float* __restrict__ lin1_b,
    const float* __restrict__ sol_w,  const float* __restrict__ sol_b,
    const float* __restrict__ tr_w,   const float* __restrict__ tr_b,
    const float* __restrict__ sc_w,   const float* __restrict__ sc_b,
    const float* __restrict__ tf_w,   const float* __restrict__ tf_b,
    const float* __restrict__ means,  const float* __restrict__ u,
    const float* __restrict__ scaling,const float* __restrict__ transform,
    float* __restrict__ out)
{
    extern __shared__ float sm[];
    float* swc  = sm + OFF_SWC;
    float* swe  = sm + OFF_SWE;
    float* swl  = sm + OFF_SWL;
    float* sbc  = sm + OFF_SBC;
    float* sbe  = sm + OFF_SBE;
    float* sbl  = sm + OFF_SBL;
    float* shw  = sm + OFF_SHW;
    float* shb  = sm + OFF_SHB;
    float* imgT = sm + OFF_IMGT;
    float* sprm = sm + OFF_SPRM;
    float* shT  = sm + OFF_SHT;
    float* sh2T = sm + OFF_SH2T;

    const int m   = blockIdx.x;
    const int tid = threadIdx.x;
    const int g0  = blockIdx.y * GPB2;
    const int od  = (m == 1 || m == 2) ? 2 : 1;

    // ---- loads ----
    for (int idx = tid; idx < 3750; idx += 256) {
        int o = idx / 75, kk = idx - o * 75;
        swc[o * 76 + kk] = conv_w[m * 3750 + idx];
    }
    for (int idx = tid; idx < 180; idx += 256) swe[idx] = emb_w[m * 180 + idx];
    for (int idx = tid; idx < 6400; idx += 256) {
        int p = idx / 80, q = idx - p * 80;
        swl[p * 84 + q] = lin1_w[m * 6400 + idx];
    }
    if (tid < 50) sbc[tid] = conv_b[m * 50 + tid];
    if (tid >= 64 && tid < 94) sbe[tid - 64] = emb_b[m * 30 + (tid - 64)];
    if (tid >= 96 && tid < 176) sbl[tid - 96] = lin1_b[m * 80 + (tid - 96)];

    const float* hw; const float* hb;
    if      (m == 0) { hw = sol_w; hb = sol_b; }
    else if (m == 1) { hw = tr_w;  hb = tr_b;  }
    else if (m == 2) { hw = sc_w;  hb = sc_b;  }
    else             { hw = tf_w;  hb = tf_b;  }
    for (int idx = tid; idx < 80 * od; idx += 256) shw[idx] = hw[idx];
    if (tid < od) shb[tid] = hb[tid];

    for (int idx = tid; idx < GPB2 * 75; idx += 256) {
        int g = idx / 75, kk = idx - g * 75;
        imgT[kk * 36 + g] = d_img[(g0 + g) * 75 + kk];
    }
    for (int idx = tid; idx < GPB2; idx += 256) {
        int i = g0 + idx;
        sprm[idx * 9 + 0] = means[2 * i];
        sprm[idx * 9 + 1] = means[2 * i + 1];
        sprm[idx * 9 + 2] = u[i];
        sprm[idx * 9 + 3] = scaling[2 * i];
        sprm[idx * 9 + 4] = scaling[2 * i + 1];
        sprm[idx * 9 + 5] = transform[i];
    }
    __syncthreads();

    // ---- stage 1: conv (2 outputs x 4 gaussians per thread, 200 tasks) ----
    if (tid < 200) {
        int ogrp = tid >> 3, ggrp = tid & 7;
        int o0 = ogrp * 2, gb = ggrp * 4;
        float b0 = sbc[o0], b1 = sbc[o0 + 1];
        float acc0[4] = {b0, b0, b0, b0};
        float acc1[4] = {b1, b1, b1, b1};
        const float* w0r = &swc[o0 * 76];
        const float* w1r = &swc[(o0 + 1) * 76];
        for (int kk = 0; kk < 75; ++kk) {
            float w0 = w0r[kk], w1 = w1r[kk];
            float4 iv = *(const float4*)&imgT[kk * 36 + gb];
            acc0[0] = fmaf(w0, iv.x, acc0[0]); acc1[0] = fmaf(w1, iv.x, acc1[0]);
            acc0[1] = fmaf(w0, iv.y, acc0[1]); acc1[1] = fmaf(w1, iv.y, acc1[1]);
            acc0[2] = fmaf(w0, iv.z, acc0[2]); acc1[2] = fmaf(w1, iv.z, acc1[2]);
            acc0[3] = fmaf(w0, iv.w, acc0[3]); acc1[3] = fmaf(w1, iv.w, acc1[3]);
        }
        #pragma unroll
        for (int b = 0; b < 4; ++b) {
            shT[o0 * 36 + gb + b]       = tanha(acc0[b]);
            shT[(o0 + 1) * 36 + gb + b] = tanha(acc1[b]);
        }
    }
    // ---- stage 1b: embedding (30 q x 8 ggrp = 240 tasks) ----
    else if (tid < 256) { } // fallthrough; emb handled below by tid<240 region
    if (tid < 240) {
        int q = tid / 8, ggrp = tid & 7;
        int gb = ggrp * 4;
        float be = sbe[q];
        float acc[4] = {be, be, be, be};
        #pragma unroll
        for (int p = 0; p < 6; ++p) {
            float w = swe[p * 30 + q];
            acc[0] = fmaf(sprm[(gb + 0) * 9 + p], w, acc[0]);
            acc[1] = fmaf(sprm[(gb + 1) * 9 + p], w, acc[1]);
            acc[2] = fmaf(sprm[(gb + 2) * 9 + p], w, acc[2]);
            acc[3] = fmaf(sprm[(gb + 3) * 9 + p], w, acc[3]);
        }
        #pragma unroll
        for (int b = 0; b < 4; ++b)
            shT[(50 + q) * 36 + gb + b] = tanha(acc[b]);
    }
    __syncthreads();

    // ---- stage 2: 80x80 (4 q x 4 g register tile, 160 tasks) ----
    if (tid < 160) {
        int qgrp = tid >> 3, ggrp = tid & 7;
        int q0 = qgrp * 4, gb = ggrp * 4;
        float acc[4][4];
        #pragma unroll
        for (int a = 0; a < 4; ++a) {
            float bl = sbl[q0 + a];
            #pragma unroll
            for (int b = 0; b < 4; ++b) acc[a][b] = bl;
        }
        for (int p = 0; p < 80; ++p) {
            float4 wv = *(const float4*)&swl[p * 84 + q0];
            float4 hv = *(const float4*)&shT[p * 36 + gb];
            acc[0][0] = fmaf(wv.x, hv.x, acc[0][0]); acc[0][1] = fmaf(wv.x, hv.y, acc[0][1]);
            acc[0][2] = fmaf(wv.x, hv.z, acc[0][2]); acc[0][3] = fmaf(wv.x, hv.w, acc[0][3]);
            acc[1][0] = fmaf(wv.y, hv.x, acc[1][0]); acc[1][1] = fmaf(wv.y, hv.y, acc[1][1]);
            acc[1][2] = fmaf(wv.y, hv.z, acc[1][2]); acc[1][3] = fmaf(wv.y, hv.w, acc[1][3]);
            acc[2][0] = fmaf(wv.z, hv.x, acc[2][0]); acc[2][1] = fmaf(wv.z, hv.y, acc[2][1]);
            acc[2][2] = fmaf(wv.z, hv.z, acc[2][2]); acc[2][3] = fmaf(wv.z, hv.w, acc[2][3]);
            acc[3][0] = fmaf(wv.w, hv.x, acc[3][0]); acc[3][1] = fmaf(wv.w, hv.y, acc[3][1]);
            acc[3][2] = fmaf(wv.w, hv.z, acc[3][2]); acc[3][3] = fmaf(wv.w, hv.w, acc[3][3]);
        }
        #pragma unroll
        for (int a = 0; a < 4; ++a)
            #pragma unroll
            for (int b = 0; b < 4; ++b)
                sh2T[(q0 + a) * 36 + gb + b] = tanha(acc[a][b]);
    }
    __syncthreads();

    // ---- head + residual update (32*od tasks) ----
    if (tid < GPB2 * od) {
        int g = tid % GPB2, d = tid / GPB2;
        float acc = shb[d];
        for (int p = 0; p < 80; ++p)
            acc = fmaf(sh2T[p * 36 + g], shw[p * od + d], acc);
        int i = g0 + g;
        if      (m == 0) out[i * 6 + 0]     = sprm[g * 9 + 2]     + acc;
        else if (m == 1) out[i * 6 + 1 + d] = sprm[g * 9 + d]     + acc;
        else if (m == 2) out[i * 6 + 3 + d] = sprm[g * 9 + 3 + d] * __expf(acc);
        else             out[i * 6 + 5]     = sprm[g * 9 + 5]     + acc;
    }
}

// ---------------------------------------------------------------------------
extern "C" void kernel_launch(void* const* d_in, const int* in_sizes, int n_in,
                              void* d_out, int out_size)
{
    const float* means     = (const float*)d_in[0];
    const float* u         = (const float*)d_in[1];
    const float* scaling   = (const float*)d_in[2];
    const float* transform = (const float*)d_in[3];
    const float* conv_w    = (const float*)d_in[4];
    const float* conv_b    = (const float*)d_in[5];
    const float* emb_w     = (const float*)d_in[6];
    const float* emb_b     = (const float*)d_in[7];
    const float* lin1_w    = (const float*)d_in[8];
    const float* lin1_b    = (const float*)d_in[9];
    const float* sol_w     = (const float*)d_in[10];
    const float* sol_b     = (const float*)d_in[11];
    const float* tr_w      = (const float*)d_in[12];
    const float* tr_b      = (const float*)d_in[13];
    const float* sc_w      = (const float*)d_in[14];
    const float* sc_b      = (const float*)d_in[15];
    const float* tf_w      = (const float*)d_in[16];
    const float* tf_b      = (const float*)d_in[17];
    float* out             = (float*)d_out;

    static int smem_set = 0;
    if (!smem_set) {
        cudaFuncSetAttribute(k_net, cudaFuncAttributeMaxDynamicSharedMemorySize,
                             SMEM_FLTS * (int)sizeof(float));
        smem_set = 1;
    }

    k_samples<<<NS / 256, 256>>>(means, u, scaling, transform);
    dim3 grid3(4, N_G / GPB2, 1);
    k_net<<<grid3, 256, SMEM_FLTS * sizeof(float)>>>(
        conv_w, conv_b, emb_w, emb_b, lin1_w, lin1_b,
        sol_w, sol_b, tr_w, tr_b, sc_w, sc_b, tf_w, tf_b,
        means, u, scaling, transform, out);
}